// round 2
// baseline (speedup 1.0000x reference)
#include <cuda_runtime.h>

#define BB 2
#define CC 64
#define HH 128
#define WW 128
#define NN 4096
#define NS 8   // B * GRID^2 slices

// ---------------- device scratch (no allocations allowed) ----------------
__device__ float g_q[NS][CC][NN];
__device__ float g_k[NS][CC][NN];
__device__ float g_a[NS][CC][NN];   // gets scaled in-place by 1/Z[j]
__device__ float g_b[NS][CC][NN];
__device__ float g_Z[NS][NN];
__device__ float g_rZ[NS][NN];
__device__ float g_o[NS][CC][NN];
__device__ float g_E[(size_t)NS * NN * NN];   // 536 MB exp(S) scratch

// ---------------- zero Z (graph replays must start clean) ----------------
__global__ void zeroZ_kernel() {
    int i = blockIdx.x * blockDim.x + threadIdx.x;
    if (i < NS * NN) (&g_Z[0][0])[i] = 0.0f;
}

// ---------------- 4 fused 1x1 convs + regionize ----------------
// block: (wtile in {0,1}, h in 0..127, b in {0,1}); 256 threads
// threads 0-63 -> q, 64-127 -> k, 128-191 -> a, 192-255 -> b
__global__ void conv4_kernel(const float* __restrict__ x,
                             const float* __restrict__ Wq, const float* __restrict__ bq,
                             const float* __restrict__ Wk, const float* __restrict__ bk,
                             const float* __restrict__ Wa, const float* __restrict__ ba,
                             const float* __restrict__ Wb, const float* __restrict__ bb) {
    __shared__ float xs[CC][64];
    int wt = blockIdx.x, h = blockIdx.y, b = blockIdx.z;
    int tid = threadIdx.x;
    for (int idx = tid; idx < CC * 64; idx += 256) {
        int c = idx >> 6, p = idx & 63;
        xs[c][p] = x[(((size_t)b * CC + c) * HH + h) * WW + wt * 64 + p];
    }
    __syncthreads();
    int p = tid & 63;
    int grp = tid >> 6;
    const float* Wm = (grp == 0) ? Wq : (grp == 1) ? Wk : (grp == 2) ? Wa : Wb;
    const float* bv = (grp == 0) ? bq : (grp == 1) ? bk : (grp == 2) ? ba : bb;
    int s = b * 4 + (h >> 6) * 2 + wt;
    int n = (h & 63) * 64 + p;
    float* outp = (grp == 0) ? &g_q[s][0][0] : (grp == 1) ? &g_k[s][0][0]
                : (grp == 2) ? &g_a[s][0][0] : &g_b[s][0][0];
    #pragma unroll 1
    for (int oc = 0; oc < CC; oc++) {
        float acc = bv[oc];
        const float4* wr = (const float4*)(Wm + oc * CC);
        #pragma unroll
        for (int c4 = 0; c4 < 16; c4++) {
            float4 w = wr[c4];
            acc += w.x * xs[c4 * 4 + 0][p] + w.y * xs[c4 * 4 + 1][p]
                 + w.z * xs[c4 * 4 + 2][p] + w.w * xs[c4 * 4 + 3][p];
        }
        outp[oc * NN + n] = acc;
    }
}

// ---------------- E = exp(q^T k / 8), Z[n] += row sums ----------------
// grid: (m-tile 64, n-tile 64, slice 8); block 256 (16x16), 4x4 microtile
__global__ void ez_kernel() {
    __shared__ float qs[CC][68];
    __shared__ float ks[CC][68];
    int s = blockIdx.z;
    int n0 = blockIdx.y * 64, m0 = blockIdx.x * 64;
    int tid = threadIdx.x;
    {
        int cbase = tid >> 4;
        int i = (tid & 15) * 4;
        #pragma unroll
        for (int r = 0; r < 4; r++) {
            int c = r * 16 + cbase;
            *(float4*)&qs[c][i] = *(const float4*)&g_q[s][c][n0 + i];
            *(float4*)&ks[c][i] = *(const float4*)&g_k[s][c][m0 + i];
        }
    }
    __syncthreads();
    int tx = tid & 15, ty = tid >> 4;
    float acc[4][4] = {};
    #pragma unroll 8
    for (int c = 0; c < CC; c++) {
        float4 q4 = *(const float4*)&qs[c][ty * 4];
        float4 k4 = *(const float4*)&ks[c][tx * 4];
        acc[0][0] += q4.x * k4.x; acc[0][1] += q4.x * k4.y; acc[0][2] += q4.x * k4.z; acc[0][3] += q4.x * k4.w;
        acc[1][0] += q4.y * k4.x; acc[1][1] += q4.y * k4.y; acc[1][2] += q4.y * k4.z; acc[1][3] += q4.y * k4.w;
        acc[2][0] += q4.z * k4.x; acc[2][1] += q4.z * k4.y; acc[2][2] += q4.z * k4.z; acc[2][3] += q4.z * k4.w;
        acc[3][0] += q4.w * k4.x; acc[3][1] += q4.w * k4.y; acc[3][2] += q4.w * k4.z; acc[3][3] += q4.w * k4.w;
    }
    #pragma unroll
    for (int u = 0; u < 4; u++) {
        float4 ev;
        ev.x = __expf(acc[u][0] * 0.125f);
        ev.y = __expf(acc[u][1] * 0.125f);
        ev.z = __expf(acc[u][2] * 0.125f);
        ev.w = __expf(acc[u][3] * 0.125f);
        int n = n0 + ty * 4 + u;
        *(float4*)&g_E[((size_t)s * NN + n) * NN + m0 + tx * 4] = ev;
        float rs = ev.x + ev.y + ev.z + ev.w;
        rs += __shfl_xor_sync(0xffffffffu, rs, 8, 16);
        rs += __shfl_xor_sync(0xffffffffu, rs, 4, 16);
        rs += __shfl_xor_sync(0xffffffffu, rs, 2, 16);
        rs += __shfl_xor_sync(0xffffffffu, rs, 1, 16);
        if (tx == 0) atomicAdd(&g_Z[s][n], rs);
    }
}

// ---------------- a *= 1/Z[j] (folds row-softmax norm of term 1); rZ ----------------
__global__ void scale_a_kernel() {
    int n = blockIdx.x * 256 + threadIdx.x;
    int c = blockIdx.y;
    int s = blockIdx.z;
    float rz = 1.0f / g_Z[s][n];
    g_a[s][c][n] *= rz;
    if (c == 0) g_rZ[s][n] = rz;
}

// ---------------- out = a' @ E + diag(1/Z) applied to b @ E^T ----------------
// grid: (m-tile 64, slice 8); block 256 (16x16); each thread 4c x 4m for both terms
__global__ void outk_kernel() {
    extern __shared__ float sm[];
    float* As  = sm;                 // [64][68]  a' (c, j)
    float* Bs  = sm + 64 * 68;       // [64][68]  b  (c, j)
    float* E1s = sm + 2 * 64 * 68;   // [64][68]  E[j][m]
    float* E2t = sm + 3 * 64 * 68;   // [64][68]  E[m][j] transposed -> [j][m]
    int s = blockIdx.y;
    int m0 = blockIdx.x * 64;
    int tid = threadIdx.x;
    int tx = tid & 15, ty = tid >> 4;
    int lc = tid >> 2;   // 0..63
    int lq = tid & 3;    // 0..3
    float o1[4][4] = {};
    float o2[4][4] = {};

    #pragma unroll 1
    for (int j0 = 0; j0 < NN; j0 += 64) {
        __syncthreads();
        #pragma unroll
        for (int f = 0; f < 4; f++) {
            int jj = lq * 4 + f * 16;
            *(float4*)&As[lc * 68 + jj]  = *(const float4*)&g_a[s][lc][j0 + jj];
            *(float4*)&Bs[lc * 68 + jj]  = *(const float4*)&g_b[s][lc][j0 + jj];
            // E1: rows j (=lc), cols m (=jj)
            *(float4*)&E1s[lc * 68 + jj] =
                *(const float4*)&g_E[((size_t)s * NN + j0 + lc) * NN + m0 + jj];
            // E2: rows m (=lc), cols j (=jj..jj+3), transpose-store as [j][m]
            float4 ve2 = *(const float4*)&g_E[((size_t)s * NN + m0 + lc) * NN + j0 + jj];
            E2t[(jj + 0) * 68 + lc] = ve2.x;
            E2t[(jj + 1) * 68 + lc] = ve2.y;
            E2t[(jj + 2) * 68 + lc] = ve2.z;
            E2t[(jj + 3) * 68 + lc] = ve2.w;
        }
        __syncthreads();
        #pragma unroll 4
        for (int j4 = 0; j4 < 16; j4++) {
            float4 e1[4], e2[4];
            #pragma unroll
            for (int d = 0; d < 4; d++) {
                e1[d] = *(const float4*)&E1s[(4 * j4 + d) * 68 + tx * 4];
                e2[d] = *(const float4*)&E2t[(4 * j4 + d) * 68 + tx * 4];
            }
            #pragma unroll
            for (int u = 0; u < 4; u++) {
                float4 av = *(const float4*)&As[(ty * 4 + u) * 68 + 4 * j4];
                float4 bv = *(const float4*)&Bs[(ty * 4 + u) * 68 + 4 * j4];
                o1[u][0] += av.x * e1[0].x + av.y * e1[1].x + av.z * e1[2].x + av.w * e1[3].x;
                o1[u][1] += av.x * e1[0].y + av.y * e1[1].y + av.z * e1[2].y + av.w * e1[3].y;
                o1[u][2] += av.x * e1[0].z + av.y * e1[1].z + av.z * e1[2].z + av.w * e1[3].z;
                o1[u][3] += av.x * e1[0].w + av.y * e1[1].w + av.z * e1[2].w + av.w * e1[3].w;
                o2[u][0] += bv.x * e2[0].x + bv.y * e2[1].x + bv.z * e2[2].x + bv.w * e2[3].x;
                o2[u][1] += bv.x * e2[0].y + bv.y * e2[1].y + bv.z * e2[2].y + bv.w * e2[3].y;
                o2[u][2] += bv.x * e2[0].z + bv.y * e2[1].z + bv.z * e2[2].z + bv.w * e2[3].z;
                o2[u][3] += bv.x * e2[0].w + bv.y * e2[1].w + bv.z * e2[2].w + bv.w * e2[3].w;
            }
        }
    }
    float4 rz = *(const float4*)&g_rZ[s][m0 + tx * 4];
    #pragma unroll
    for (int u = 0; u < 4; u++) {
        float4 res;
        res.x = o1[u][0] + o2[u][0] * rz.x;
        res.y = o1[u][1] + o2[u][1] * rz.y;
        res.z = o1[u][2] + o2[u][2] * rz.z;
        res.w = o1[u][3] + o2[u][3] * rz.w;
        *(float4*)&g_o[s][ty * 4 + u][m0 + tx * 4] = res;
    }
}

// ---------------- final 1x1 conv + un-regionize ----------------
__global__ void finalconv_kernel(const float* __restrict__ Wo, const float* __restrict__ bo,
                                 float* __restrict__ out) {
    __shared__ float os[CC][64];
    int wt = blockIdx.x, h = blockIdx.y, b = blockIdx.z;
    int tid = threadIdx.x;
    int s = b * 4 + (h >> 6) * 2 + wt;
    int nbase = (h & 63) * 64;
    for (int idx = tid; idx < CC * 64; idx += 256) {
        int c = idx >> 6, p = idx & 63;
        os[c][p] = g_o[s][c][nbase + p];
    }
    __syncthreads();
    int p = tid & 63, grp = tid >> 6;
    #pragma unroll 1
    for (int i = 0; i < 16; i++) {
        int oc = grp * 16 + i;
        float acc = bo[oc];
        const float4* wr = (const float4*)(Wo + oc * CC);
        #pragma unroll
        for (int c4 = 0; c4 < 16; c4++) {
            float4 w = wr[c4];
            acc += w.x * os[c4 * 4 + 0][p] + w.y * os[c4 * 4 + 1][p]
                 + w.z * os[c4 * 4 + 2][p] + w.w * os[c4 * 4 + 3][p];
        }
        out[(((size_t)b * CC + oc) * HH + h) * WW + wt * 64 + p] = acc;
    }
}

// ---------------- launch ----------------
extern "C" void kernel_launch(void* const* d_in, const int* in_sizes, int n_in,
                              void* d_out, int out_size) {
    const float* x  = (const float*)d_in[0];
    const float* Wq = (const float*)d_in[1];
    const float* bq = (const float*)d_in[2];
    const float* Wk = (const float*)d_in[3];
    const float* bk = (const float*)d_in[4];
    const float* Wa = (const float*)d_in[5];
    const float* ba = (const float*)d_in[6];
    const float* Wb = (const float*)d_in[7];
    const float* bb = (const float*)d_in[8];
    const float* Wo = (const float*)d_in[9];
    const float* bo = (const float*)d_in[10];
    float* out = (float*)d_out;

    const int outk_smem = 4 * 64 * 68 * (int)sizeof(float);   // 69632 B
    cudaFuncSetAttribute(outk_kernel, cudaFuncAttributeMaxDynamicSharedMemorySize, outk_smem);

    zeroZ_kernel<<<(NS * NN + 255) / 256, 256>>>();
    conv4_kernel<<<dim3(2, HH, BB), 256>>>(x, Wq, bq, Wk, bk, Wa, ba, Wb, bb);
    ez_kernel<<<dim3(64, 64, NS), 256>>>();
    scale_a_kernel<<<dim3(NN / 256, CC, NS), 256>>>();
    outk_kernel<<<dim3(64, NS), 256, outk_smem>>>();
    finalconv_kernel<<<dim3(2, HH, BB), 256>>>(Wo, bo, out);
}